// round 2
// baseline (speedup 1.0000x reference)
#include <cuda_runtime.h>
#include <cuda_bf16.h>

#define A_N   49104
#define B_N   8
#define C_N   80
#define M_N   64
#define TPB   256
#define NWARP (TPB/32)

// Per-batch accumulators (graph-safe device globals; zeroed every launch)
__device__ double g_cls_sum[B_N];
__device__ double g_reg_sum[B_N];
__device__ int    g_npos[B_N];

__global__ void fl_init_kernel() {
    int i = threadIdx.x;
    if (i < B_N) { g_cls_sum[i] = 0.0; g_reg_sum[i] = 0.0; g_npos[i] = 0; }
}

__device__ __forceinline__ float smooth_l1(float d) {
    return (d <= (1.0f/9.0f)) ? 4.5f * d * d : d - (0.5f/9.0f);
}

__global__ __launch_bounds__(TPB) void fl_main_kernel(
    const float* __restrict__ reg,    // [B, A, 4]
    const float* __restrict__ cls,    // [B, A, C]
    const float* __restrict__ anc,    // [1, A, 4]
    const float* __restrict__ gt)     // [B, M, 5]
{
    __shared__ float4 s_gbox[M_N];
    __shared__ float  s_garea[M_N];
    __shared__ float  s_gcls[M_N];
    __shared__ float  s_rc[NWARP];
    __shared__ float  s_rr[NWARP];
    __shared__ int    s_rn[NWARP];

    const int b   = blockIdx.y;
    const int tid = threadIdx.x;

    // Load this batch's GT boxes into smem (M=64 rows of 5 floats)
    if (tid < M_N) {
        const float* g = gt + ((size_t)b * M_N + tid) * 5;
        float x1 = g[0], y1 = g[1], x2 = g[2], y2 = g[3], c = g[4];
        if (c < 0.0f) { x1 = y1 = x2 = y2 = 0.0f; } // invalid gt -> empty box (never wins argmax)
        s_gbox[tid]  = make_float4(x1, y1, x2, y2);
        s_garea[tid] = (x2 - x1) * (y2 - y1);
        s_gcls[tid]  = c;
    }
    __syncthreads();

    const int a = blockIdx.x * TPB + tid;

    unsigned code = 0u;       // bit0: pos, bit1: active (pos or neg), bits8+: class id
    float accC = 0.0f;        // sum of w*q^2*log2(1-q)  (negative)
    float accR = 0.0f;        // smooth-L1 sum for pos anchors
    int   npos = 0;

    if (a < A_N) {
        const float4 ab = *reinterpret_cast<const float4*>(anc + (size_t)a * 4);
        const float aw  = fabsf(ab.x - ab.z);
        const float ah  = fabsf(ab.y - ab.w);
        const float acx = ab.x + 0.5f * aw;
        const float acy = ab.y + 0.5f * ah;
        const float a_area = (ab.z - ab.x) * (ab.w - ab.y);

        // ---- IoU argmax over M gts. Track (inter, S=a_area+g_area); compare
        //      i1/(S1-i1) > i2/(S2-i2)  <=>  i1*S2 > i2*S1   (unions > 0). ----
        float bI = 0.0f, bS = 1.0f;
        int   bidx = 0;
        #pragma unroll 8
        for (int m = 0; m < M_N; m++) {
            const float4 gb = s_gbox[m];
            float iw = fminf(ab.z, gb.z) - fmaxf(ab.x, gb.x);
            float ih = fminf(ab.w, gb.w) - fmaxf(ab.y, gb.y);
            float inter = fmaxf(iw, 0.0f) * fmaxf(ih, 0.0f);
            float S = a_area + s_garea[m];
            if (inter * bS > bI * S) { bI = inter; bS = S; bidx = m; }
        }
        // iou = bI/(bS-bI):  iou>=0.5 <=> 3I>=S ;  iou<0.4 <=> 7I<2S
        const bool pos = (3.0f * bI >= bS);
        const bool neg = (7.0f * bI < 2.0f * bS);

        if (pos) {
            const float4 gb = s_gbox[bidx];
            float gw0 = gb.z - gb.x, gh0 = gb.w - gb.y;
            float gcx = gb.x + 0.5f * gw0, gcy = gb.y + 0.5f * gh0;
            float gw = fmaxf(gw0, 1.0f), gh = fmaxf(gh0, 1.0f);
            float tdx = __fdividef(gcx - acx, aw);
            float tdy = __fdividef(gcy - acy, ah);
            float tdh = __logf(__fdividef(gh, ah));
            float tdw = __logf(__fdividef(gw, aw));
            const float4 rg = *reinterpret_cast<const float4*>(reg + ((size_t)b * A_N + a) * 4);
            accR = smooth_l1(fabsf(tdx - rg.x)) + smooth_l1(fabsf(tdy - rg.y))
                 + smooth_l1(fabsf(tdh - rg.z)) + smooth_l1(fabsf(tdw - rg.w));
            npos = 1;
            int cid = (int)s_gcls[bidx];
            code = 3u | ((unsigned)cid << 8);
        } else if (neg) {
            code = 2u;
        }
    }

    // ---- Phase 2: warp-cooperative focal loss, coalesced row reads ----
    const int lane  = tid & 31;
    const int wbase = blockIdx.x * TPB + (tid & ~31);
    const float* clsb = cls + (size_t)b * A_N * C_N;

    #pragma unroll 1
    for (int j = 0; j < 32; j++) {
        const unsigned cj = __shfl_sync(0xffffffffu, code, j);
        if (!(cj & 2u)) continue;                    // ignore-region / inactive anchor
        const float* row = clsb + (size_t)(wbase + j) * C_N;
        const int cid = (cj & 1u) ? (int)(cj >> 8) : -1;

        const float p0 = row[lane];
        const float p1 = row[lane + 32];
        {
            float pc = fminf(fmaxf(p0, 1e-4f), 1.0f - 1e-4f);
            bool  t1 = (lane == cid);
            float q  = t1 ? 1.0f - pc : pc;
            float w  = t1 ? 0.25f : 0.75f;
            accC += w * q * q * __log2f(1.0f - q);
        }
        {
            float pc = fminf(fmaxf(p1, 1e-4f), 1.0f - 1e-4f);
            bool  t1 = (lane + 32 == cid);
            float q  = t1 ? 1.0f - pc : pc;
            float w  = t1 ? 0.25f : 0.75f;
            accC += w * q * q * __log2f(1.0f - q);
        }
        if (lane < 16) {
            const float p2 = row[lane + 64];
            float pc = fminf(fmaxf(p2, 1e-4f), 1.0f - 1e-4f);
            bool  t1 = (lane + 64 == cid);
            float q  = t1 ? 1.0f - pc : pc;
            float w  = t1 ? 0.25f : 0.75f;
            accC += w * q * q * __log2f(1.0f - q);
        }
    }

    // ---- Block reduction ----
    #pragma unroll
    for (int o = 16; o > 0; o >>= 1) {
        accC += __shfl_down_sync(0xffffffffu, accC, o);
        accR += __shfl_down_sync(0xffffffffu, accR, o);
        npos += __shfl_down_sync(0xffffffffu, npos, o);
    }
    if (lane == 0) { s_rc[tid >> 5] = accC; s_rr[tid >> 5] = accR; s_rn[tid >> 5] = npos; }
    __syncthreads();
    if (tid == 0) {
        float c = 0.0f, r = 0.0f; int n = 0;
        #pragma unroll
        for (int w = 0; w < NWARP; w++) { c += s_rc[w]; r += s_rr[w]; n += s_rn[w]; }
        atomicAdd(&g_cls_sum[b], (double)c);
        atomicAdd(&g_reg_sum[b], (double)r);
        atomicAdd(&g_npos[b], n);
    }
}

__global__ void fl_fin_kernel(float* __restrict__ out) {
    if (threadIdx.x == 0 && blockIdx.x == 0) {
        const double NEG_LN2 = -0.6931471805599453;
        float cs = 0.0f, rs = 0.0f;
        #pragma unroll
        for (int b = 0; b < B_N; b++) {
            int   n  = g_npos[b];
            float nf = (float)n;
            float cl = (float)(NEG_LN2 * g_cls_sum[b]) / fmaxf(nf, 1.0f);
            float rl = (n > 0) ? (float)g_reg_sum[b] / fmaxf(4.0f * nf, 1.0f) : 0.0f;
            cs += cl; rs += rl;
        }
        out[0] = cs * (1.0f / 8.0f);
        out[1] = rs * (1.0f / 8.0f) * 50.0f;
    }
}

extern "C" void kernel_launch(void* const* d_in, const int* in_sizes, int n_in,
                              void* d_out, int out_size) {
    const float* regression     = (const float*)d_in[0];
    const float* classification = (const float*)d_in[1];
    const float* anchors        = (const float*)d_in[2];
    const float* gt_BB          = (const float*)d_in[3];
    float* out = (float*)d_out;

    fl_init_kernel<<<1, 32>>>();
    dim3 grid((A_N + TPB - 1) / TPB, B_N);
    fl_main_kernel<<<grid, TPB>>>(regression, classification, anchors, gt_BB);
    fl_fin_kernel<<<1, 32>>>(out);
}

// round 3
// speedup vs baseline: 1.0775x; 1.0775x over previous
#include <cuda_runtime.h>
#include <cuda_bf16.h>

#define A_N   49104
#define B_N   8
#define C_N   80
#define M_N   64
#define TPB   256
#define NWARP (TPB/32)
#define EPSV  1e-4f

// Per-batch accumulators (graph-safe device globals; zeroed every launch)
__device__ double g_cls_sum[B_N];
__device__ double g_reg_sum[B_N];
__device__ int    g_npos[B_N];

__global__ void fl_init_kernel() {
    int i = threadIdx.x;
    if (i < B_N) { g_cls_sum[i] = 0.0; g_reg_sum[i] = 0.0; g_npos[i] = 0; }
}

__device__ __forceinline__ float smooth_l1(float d) {
    return (d <= (1.0f/9.0f)) ? 4.5f * d * d : d - (0.5f/9.0f);
}

// Unscaled negative-target term: pc^2 * log2(1-pc). (x0.75, x-ln2 applied later)
__device__ __forceinline__ float baseterm(float p) {
    float pc = fminf(fmaxf(p, EPSV), 1.0f - EPSV);
    return pc * pc * __log2f(1.0f - pc);
}
// Fully-scaled positive-target term: 0.25 * (1-pc)^2 * log2(pc)
__device__ __forceinline__ float posterm(float p) {
    float pc = fminf(fmaxf(p, EPSV), 1.0f - EPSV);
    float q  = 1.0f - pc;
    return 0.25f * q * q * __log2f(pc);
}

__global__ __launch_bounds__(TPB) void fl_main_kernel(
    const float* __restrict__ reg,    // [B, A, 4]
    const float* __restrict__ cls,    // [B, A, C]
    const float* __restrict__ anc,    // [1, A, 4]
    const float* __restrict__ gt)     // [B, M, 5]
{
    __shared__ float4 s_gbox[M_N];
    __shared__ float  s_garea[M_N];
    __shared__ int    s_gcls[M_N];
    __shared__ int    s_code[TPB];
    __shared__ float  s_rc[NWARP];
    __shared__ float  s_rr[NWARP];
    __shared__ int    s_rn[NWARP];

    const int b   = blockIdx.y;
    const int tid = threadIdx.x;

    if (tid < M_N) {
        const float* g = gt + ((size_t)b * M_N + tid) * 5;
        float x1 = g[0], y1 = g[1], x2 = g[2], y2 = g[3], c = g[4];
        if (c < 0.0f) { x1 = y1 = x2 = y2 = 0.0f; } // invalid gt -> never wins argmax
        s_gbox[tid]  = make_float4(x1, y1, x2, y2);
        s_garea[tid] = (x2 - x1) * (y2 - y1);
        s_gcls[tid]  = (int)c;
    }
    __syncthreads();

    const int a = blockIdx.x * TPB + tid;

    // code: -2 = inactive (ignore region / out of range), -1 = negative, >=0 = positive class id
    int   code = -2;
    float accB = 0.0f;   // unscaled sum of pc^2*log2(1-pc)
    float accS = 0.0f;   // fully scaled pos-term sum
    float accR = 0.0f;   // smooth-L1 sum
    int   npos = 0;

    if (a < A_N) {
        const float4 ab = *reinterpret_cast<const float4*>(anc + (size_t)a * 4);
        const float aw  = fabsf(ab.x - ab.z);
        const float ah  = fabsf(ab.y - ab.w);
        const float acx = ab.x + 0.5f * aw;
        const float acy = ab.y + 0.5f * ah;
        const float a_area = (ab.z - ab.x) * (ab.w - ab.y);

        // IoU argmax over M gts. Track (inter, S=a_area+g_area);
        // i1/(S1-i1) > i2/(S2-i2)  <=>  i1*S2 > i2*S1  (unions > 0).
        float bI = 0.0f, bS = 1.0f;
        int   bidx = 0;
        #pragma unroll 8
        for (int m = 0; m < M_N; m++) {
            const float4 gb = s_gbox[m];
            float iw = fminf(ab.z, gb.z) - fmaxf(ab.x, gb.x);
            float ih = fminf(ab.w, gb.w) - fmaxf(ab.y, gb.y);
            float inter = fmaxf(iw, 0.0f) * fmaxf(ih, 0.0f);
            float S = a_area + s_garea[m];
            if (inter * bS > bI * S) { bI = inter; bS = S; bidx = m; }
        }
        // iou >= 0.5 <=> 3I >= S ;  iou < 0.4 <=> 7I < 2S
        const bool pos = (3.0f * bI >= bS);
        const bool neg = (7.0f * bI < 2.0f * bS);

        if (pos) {
            const float4 gb = s_gbox[bidx];
            float gw0 = gb.z - gb.x, gh0 = gb.w - gb.y;
            float gcx = gb.x + 0.5f * gw0, gcy = gb.y + 0.5f * gh0;
            float gw = fmaxf(gw0, 1.0f), gh = fmaxf(gh0, 1.0f);
            float tdx = __fdividef(gcx - acx, aw);
            float tdy = __fdividef(gcy - acy, ah);
            float tdh = __logf(__fdividef(gh, ah));
            float tdw = __logf(__fdividef(gw, aw));
            const float4 rg = *reinterpret_cast<const float4*>(reg + ((size_t)b * A_N + a) * 4);
            accR = smooth_l1(fabsf(tdx - rg.x)) + smooth_l1(fabsf(tdy - rg.y))
                 + smooth_l1(fabsf(tdh - rg.z)) + smooth_l1(fabsf(tdw - rg.w));
            npos = 1;
            code = s_gcls[bidx];
        } else if (neg) {
            code = -1;
        }
    }
    s_code[tid] = code;
    __syncwarp();

    // ---- Phase 2: streaming focal loss over this warp's 32 anchor rows ----
    const int lane  = tid & 31;
    const int sbase = tid & ~31;
    const int wbase = blockIdx.x * TPB + sbase;
    const float* clsb = cls + (size_t)b * A_N * C_N;

    if (wbase + 32 <= A_N) {
        // Fast path: 32 rows x 80 floats = 640 float4, fully coalesced & unrolled.
        const float4* wp = reinterpret_cast<const float4*>(clsb + (size_t)wbase * C_N);
        #pragma unroll
        for (int k = 0; k < 20; k++) {
            const int f  = lane + 32 * k;       // float4 index within warp chunk
            const int al = f / 20;              // local anchor (20 float4 per row)
            const int c0 = (f - al * 20) * 4;   // class index of .x
            const int cj = s_code[sbase + al];
            const float4 pv = wp[f];
            if (cj == -1) {
                accB += baseterm(pv.x) + baseterm(pv.y) + baseterm(pv.z) + baseterm(pv.w);
            } else if (cj >= 0) {
                if (c0 + 0 == cj) accS += posterm(pv.x); else accB += baseterm(pv.x);
                if (c0 + 1 == cj) accS += posterm(pv.y); else accB += baseterm(pv.y);
                if (c0 + 2 == cj) accS += posterm(pv.z); else accB += baseterm(pv.z);
                if (c0 + 3 == cj) accS += posterm(pv.w); else accB += baseterm(pv.w);
            }
            // cj == -2: ignore region contributes nothing
        }
    } else {
        // Tail path (last block's partial warps only): per-anchor, guarded.
        for (int j = 0; j < 32; j++) {
            const int anchor = wbase + j;
            if (anchor >= A_N) break;
            const int cj = s_code[sbase + j];
            if (cj == -2) continue;
            const float* row = clsb + (size_t)anchor * C_N;
            {
                float p = row[lane];
                if (lane == cj) accS += posterm(p); else accB += baseterm(p);
            }
            {
                float p = row[lane + 32];
                if (lane + 32 == cj) accS += posterm(p); else accB += baseterm(p);
            }
            if (lane < 16) {
                float p = row[lane + 64];
                if (lane + 64 == cj) accS += posterm(p); else accB += baseterm(p);
            }
        }
    }

    float accC = 0.75f * accB + accS;

    // ---- Block reduction ----
    #pragma unroll
    for (int o = 16; o > 0; o >>= 1) {
        accC += __shfl_down_sync(0xffffffffu, accC, o);
        accR += __shfl_down_sync(0xffffffffu, accR, o);
        npos += __shfl_down_sync(0xffffffffu, npos, o);
    }
    if (lane == 0) { s_rc[tid >> 5] = accC; s_rr[tid >> 5] = accR; s_rn[tid >> 5] = npos; }
    __syncthreads();
    if (tid == 0) {
        float c = 0.0f, r = 0.0f; int n = 0;
        #pragma unroll
        for (int w = 0; w < NWARP; w++) { c += s_rc[w]; r += s_rr[w]; n += s_rn[w]; }
        atomicAdd(&g_cls_sum[b], (double)c);
        atomicAdd(&g_reg_sum[b], (double)r);
        atomicAdd(&g_npos[b], n);
    }
}

__global__ void fl_fin_kernel(float* __restrict__ out) {
    if (threadIdx.x == 0 && blockIdx.x == 0) {
        const double NEG_LN2 = -0.6931471805599453;
        float cs = 0.0f, rs = 0.0f;
        #pragma unroll
        for (int b = 0; b < B_N; b++) {
            int   n  = g_npos[b];
            float nf = (float)n;
            float cl = (float)(NEG_LN2 * g_cls_sum[b]) / fmaxf(nf, 1.0f);
            float rl = (n > 0) ? (float)g_reg_sum[b] / fmaxf(4.0f * nf, 1.0f) : 0.0f;
            cs += cl; rs += rl;
        }
        out[0] = cs * (1.0f / 8.0f);
        out[1] = rs * (1.0f / 8.0f) * 50.0f;
    }
}

extern "C" void kernel_launch(void* const* d_in, const int* in_sizes, int n_in,
                              void* d_out, int out_size) {
    const float* regression     = (const float*)d_in[0];
    const float* classification = (const float*)d_in[1];
    const float* anchors        = (const float*)d_in[2];
    const float* gt_BB          = (const float*)d_in[3];
    float* out = (float*)d_out;

    fl_init_kernel<<<1, 32>>>();
    dim3 grid((A_N + TPB - 1) / TPB, B_N);
    fl_main_kernel<<<grid, TPB>>>(regression, classification, anchors, gt_BB);
    fl_fin_kernel<<<1, 32>>>(out);
}

// round 4
// speedup vs baseline: 1.4551x; 1.3504x over previous
#include <cuda_runtime.h>
#include <cuda_bf16.h>

#define A_N   49104
#define B_N   8
#define C_N   80
#define M_N   64
#define TPB   256
#define XBLK  ((A_N + TPB - 1) / TPB)   /* 192 */
#define NBLK  (XBLK * B_N)              /* 1536 */
#define NWARP (TPB/32)
#define EPSV  1e-4f

// Per-block partials (fully overwritten each launch before being read)
__device__ float    p_cls[NBLK];
__device__ float    p_reg[NBLK];
__device__ int      p_np[NBLK];
__device__ unsigned g_done = 0;         // reset by last block each launch

__device__ __forceinline__ float smooth_l1(float d) {
    return (d <= (1.0f/9.0f)) ? 4.5f * d * d : d - (0.5f/9.0f);
}
// Unscaled negative-target term: pc^2 * log2(1-pc). (-ln2 and 0.75 folded later)
__device__ __forceinline__ float baseterm(float p) {
    float pc = fminf(fmaxf(p, EPSV), 1.0f - EPSV);
    return pc * pc * __log2f(1.0f - pc);
}
// Positive-class term with alpha folded: 0.25 * (1-pc)^2 * log2(pc)
__device__ __forceinline__ float posterm(float p) {
    float pc = fminf(fmaxf(p, EPSV), 1.0f - EPSV);
    float q  = 1.0f - pc;
    return 0.25f * q * q * __log2f(pc);
}

__global__ __launch_bounds__(TPB) void fl_main_kernel(
    const float* __restrict__ reg,    // [B, A, 4]
    const float* __restrict__ cls,    // [B, A, C]
    const float* __restrict__ anc,    // [1, A, 4]
    const float* __restrict__ gt,     // [B, M, 5]
    float* __restrict__ out)          // [2]
{
    __shared__ float4 s_gbox[M_N];
    __shared__ float  s_garea[M_N];
    __shared__ int    s_gcls[M_N];
    __shared__ float  s_flag[TPB];    // 0 = ignore/inactive, 0.75 = active (pos or neg)
    __shared__ float  s_rc[NWARP];
    __shared__ float  s_rr[NWARP];
    __shared__ int    s_rn[NWARP];
    __shared__ float  s_bl[2 * B_N];  // finalize scratch
    __shared__ bool   s_last;

    const int b   = blockIdx.y;
    const int tid = threadIdx.x;

    if (tid < M_N) {
        const float* g = gt + ((size_t)b * M_N + tid) * 5;
        float x1 = g[0], y1 = g[1], x2 = g[2], y2 = g[3], c = g[4];
        if (c < 0.0f) { x1 = y1 = x2 = y2 = 0.0f; }  // invalid gt -> never wins argmax
        s_gbox[tid]  = make_float4(x1, y1, x2, y2);
        s_garea[tid] = (x2 - x1) * (y2 - y1);
        s_gcls[tid]  = (int)c;
    }
    __syncthreads();

    const int a = blockIdx.x * TPB + tid;
    const float* clsb = cls + (size_t)b * A_N * C_N;

    float flag = 0.0f;   // focal weight for base stream (0 or 0.75)
    float accB = 0.0f;   // sum of flag * pc^2*log2(1-pc)
    float accS = 0.0f;   // pos-class corrections (fully alpha-scaled, log2 units)
    float accR = 0.0f;   // smooth-L1 sum
    int   npos = 0;

    if (a < A_N) {
        const float4 ab = *reinterpret_cast<const float4*>(anc + (size_t)a * 4);
        const float aw  = fabsf(ab.x - ab.z);
        const float ah  = fabsf(ab.y - ab.w);
        const float acx = ab.x + 0.5f * aw;
        const float acy = ab.y + 0.5f * ah;
        const float a_area = (ab.z - ab.x) * (ab.w - ab.y);

        // IoU argmax via r = inter/(a_area+g_area); iou = r/(1-r) monotone in r.
        float rbest = -1.0f;
        int   bidx  = 0;
        #pragma unroll 16
        for (int m = 0; m < M_N; m++) {
            const float4 gb = s_gbox[m];
            float iw = fmaxf(fminf(ab.z, gb.z) - fmaxf(ab.x, gb.x), 0.0f);
            float ih = fmaxf(fminf(ab.w, gb.w) - fmaxf(ab.y, gb.y), 0.0f);
            float inter = iw * ih;
            float S = a_area + s_garea[m];
            float r = inter * __frcp_rn(S);
            bidx  = (r > rbest) ? m : bidx;
            rbest = fmaxf(r, rbest);
        }
        // iou >= 0.5 <=> r >= 1/3 ; iou < 0.4 <=> r < 2/7
        const bool pos = (rbest >= (1.0f/3.0f));
        const bool neg = (rbest <  (2.0f/7.0f));
        if (pos | neg) flag = 0.75f;

        if (pos) {
            const float4 gb = s_gbox[bidx];
            float gw0 = gb.z - gb.x, gh0 = gb.w - gb.y;
            float gcx = gb.x + 0.5f * gw0, gcy = gb.y + 0.5f * gh0;
            float gw = fmaxf(gw0, 1.0f), gh = fmaxf(gh0, 1.0f);
            float tdx = __fdividef(gcx - acx, aw);
            float tdy = __fdividef(gcy - acy, ah);
            float tdh = __logf(__fdividef(gh, ah));
            float tdw = __logf(__fdividef(gw, aw));
            const float4 rg = *reinterpret_cast<const float4*>(reg + ((size_t)b * A_N + a) * 4);
            accR = smooth_l1(fabsf(tdx - rg.x)) + smooth_l1(fabsf(tdy - rg.y))
                 + smooth_l1(fabsf(tdh - rg.z)) + smooth_l1(fabsf(tdw - rg.w));
            npos = 1;
            // Positive-class correction: replace 0.75*base with the alpha term
            const int cid = s_gcls[bidx];
            const float p = clsb[(size_t)a * C_N + cid];
            accS = posterm(p) - 0.75f * baseterm(p);
        }
    }
    s_flag[tid] = flag;
    __syncwarp();

    // ---- Phase 2: branchless focal base stream over this warp's 32 rows ----
    const int lane  = tid & 31;
    const int sbase = tid & ~31;
    const int wbase = blockIdx.x * TPB + sbase;

    if (wbase + 32 <= A_N) {
        const float4* wp = reinterpret_cast<const float4*>(clsb + (size_t)wbase * C_N);
        #pragma unroll
        for (int k = 0; k < 20; k++) {
            const int f  = lane + 32 * k;
            const int al = f / 20;                 // 20 float4 per 80-class row
            const float fl = s_flag[sbase + al];
            const float4 pv = wp[f];
            float t = baseterm(pv.x) + baseterm(pv.y) + baseterm(pv.z) + baseterm(pv.w);
            accB = fmaf(fl, t, accB);
        }
    } else {
        // Tail (last x-block only)
        const float4* wp = reinterpret_cast<const float4*>(clsb + (size_t)wbase * C_N);
        for (int k = 0; k < 20; k++) {
            const int f  = lane + 32 * k;
            const int al = f / 20;
            if (wbase + al < A_N) {
                const float fl = s_flag[sbase + al];
                const float4 pv = wp[f];
                float t = baseterm(pv.x) + baseterm(pv.y) + baseterm(pv.z) + baseterm(pv.w);
                accB = fmaf(fl, t, accB);
            }
        }
    }

    float accC = accB + accS;

    // ---- Block reduction -> per-block partials ----
    #pragma unroll
    for (int o = 16; o > 0; o >>= 1) {
        accC += __shfl_down_sync(0xffffffffu, accC, o);
        accR += __shfl_down_sync(0xffffffffu, accR, o);
        npos += __shfl_down_sync(0xffffffffu, npos, o);
    }
    if (lane == 0) { s_rc[tid >> 5] = accC; s_rr[tid >> 5] = accR; s_rn[tid >> 5] = npos; }
    __syncthreads();

    const int blk = b * XBLK + blockIdx.x;
    if (tid == 0) {
        float c = 0.0f, r = 0.0f; int n = 0;
        #pragma unroll
        for (int w = 0; w < NWARP; w++) { c += s_rc[w]; r += s_rr[w]; n += s_rn[w]; }
        p_cls[blk] = c; p_reg[blk] = r; p_np[blk] = n;
        __threadfence();
        unsigned done = atomicAdd(&g_done, 1u);
        s_last = (done == NBLK - 1);
    }
    __syncthreads();

    // ---- Last block finalizes ----
    if (s_last) {
        __threadfence();
        const int w = tid >> 5;
        if (w < B_N) {
            float c = 0.0f, r = 0.0f; float n = 0.0f;
            for (int i = lane; i < XBLK; i += 32) {
                const int idx = w * XBLK + i;
                c += p_cls[idx]; r += p_reg[idx]; n += (float)p_np[idx];
            }
            #pragma unroll
            for (int o = 16; o > 0; o >>= 1) {
                c += __shfl_down_sync(0xffffffffu, c, o);
                r += __shfl_down_sync(0xffffffffu, r, o);
                n += __shfl_down_sync(0xffffffffu, n, o);
            }
            if (lane == 0) {
                const float NEG_LN2 = -0.69314718055994530942f;
                s_bl[w]       = NEG_LN2 * c / fmaxf(n, 1.0f);
                s_bl[B_N + w] = (n > 0.0f) ? r / (4.0f * n) : 0.0f;
            }
        }
        __syncthreads();
        if (tid == 0) {
            float cs = 0.0f, rs = 0.0f;
            #pragma unroll
            for (int i = 0; i < B_N; i++) { cs += s_bl[i]; rs += s_bl[B_N + i]; }
            out[0] = cs * (1.0f / (float)B_N);
            out[1] = rs * (1.0f / (float)B_N) * 50.0f;
            atomicExch(&g_done, 0u);   // reset for next launch / graph replay
        }
    }
}

extern "C" void kernel_launch(void* const* d_in, const int* in_sizes, int n_in,
                              void* d_out, int out_size) {
    const float* regression     = (const float*)d_in[0];
    const float* classification = (const float*)d_in[1];
    const float* anchors        = (const float*)d_in[2];
    const float* gt_BB          = (const float*)d_in[3];
    float* out = (float*)d_out;

    dim3 grid(XBLK, B_N);
    fl_main_kernel<<<grid, TPB>>>(regression, classification, anchors, gt_BB, out);
}